// round 6
// baseline (speedup 1.0000x reference)
#include <cuda_runtime.h>
#include <cuda_bf16.h>

#define N_NODES 100000
#define N_EDGES 1600000
#define HID 64
#define NGRAPH 128
#define DENSE 128
#define SCAN_BLK 4096
#define NB ((N_NODES + SCAN_BLK - 1) / SCAN_BLK)   // 25

// Scratch
__device__ float           g_buf0[N_NODES * HID];  // h (post-relu, fp32 gemm input)
__device__ __nv_bfloat16   g_gath[N_NODES * HID];  // (h@W)*dinv, bf16 gather buffer
__device__ int    g_cnt[N_NODES];                  // zeroed at end of fill_k each call
__device__ int    g_rowptr[N_NODES + 1];
__device__ int    g_rank[N_EDGES];                 // edge rank within dst (from hist)
__device__ int    g_col[N_EDGES];
__device__ float  g_dinv[N_NODES];
__device__ float4 g_xd[N_NODES];                   // x * dinv[src], padded
__device__ int    g_bsum[NB];

// ---------------------------------------------------------------- CSR build
// Histogram; atomic return value = rank of edge within its destination.
__global__ void hist_k(const int* __restrict__ ei) {
    int i = blockIdx.x * blockDim.x + threadIdx.x;   // 4 edges per thread
    if (i < N_EDGES / 4) {
        int4 d = ((const int4*)(ei + N_EDGES))[i];
        int4 r;
        r.x = atomicAdd(&g_cnt[d.x], 1);
        r.y = atomicAdd(&g_cnt[d.y], 1);
        r.z = atomicAdd(&g_cnt[d.z], 1);
        r.w = atomicAdd(&g_cnt[d.w], 1);
        ((int4*)g_rank)[i] = r;
    }
}

// Per-block local exclusive scan (4096 elems / block), block total to g_bsum.
__global__ void scan1_k() {
    __shared__ int sh[1024];
    int tid = threadIdx.x;
    int base = blockIdx.x * SCAN_BLK;
    int v[4];
    int local = 0;
#pragma unroll
    for (int q = 0; q < 4; q++) {
        int i = base + tid * 4 + q;
        v[q] = (i < N_NODES) ? g_cnt[i] : 0;
        local += v[q];
    }
    sh[tid] = local;
    for (int off = 1; off < 1024; off <<= 1) {
        __syncthreads();
        int t = (tid >= off) ? sh[tid - off] : 0;
        __syncthreads();
        sh[tid] += t;
    }
    __syncthreads();
    int run = sh[tid] - local;
#pragma unroll
    for (int q = 0; q < 4; q++) {
        int i = base + tid * 4 + q;
        if (i < N_NODES) { g_rowptr[i] = run; run += v[q]; }
    }
    if (tid == 1023) g_bsum[blockIdx.x] = sh[1023];
}

// Add block offsets (redundant per-block warp scan over g_bsum);
// compute dinv and xd = x*dinv.
__global__ void scan3_k(const float* __restrict__ x) {
    __shared__ int off_s;
    __shared__ int tot_s;
    int t = threadIdx.x;
    if (t < 32) {
        int myblk = (blockIdx.x * blockDim.x) / SCAN_BLK;  // 256-thr blocks never straddle
        int v = (t < NB) ? g_bsum[t] : 0;
        int pre = (t < myblk) ? v : 0;
        int tot = v;
#pragma unroll
        for (int o = 16; o; o >>= 1) {
            pre += __shfl_xor_sync(0xffffffffu, pre, o);
            tot += __shfl_xor_sync(0xffffffffu, tot, o);
        }
        if (t == 0) { off_s = pre; tot_s = tot; }
    }
    __syncthreads();
    int i = blockIdx.x * blockDim.x + t;
    if (i < N_NODES) {
        g_rowptr[i] += off_s;
        float di = rsqrtf((float)(g_cnt[i] + 1));   // +1 self loop
        g_dinv[i] = di;
        float x0 = x[i * 3 + 0], x1 = x[i * 3 + 1], x2 = x[i * 3 + 2];
        g_xd[i] = make_float4(x0 * di, x1 * di, x2 * di, 0.f);
    }
    if (blockIdx.x == 0 && t == 0) g_rowptr[N_NODES] = tot_s;
}

// Atomic-free fill: pos = rowptr[dst] + rank[edge]. Also re-zeroes g_cnt
// (safe: scan3_k was the last reader; keeps the invariant cnt==0 at entry of
// the next execution's hist_k).
__global__ void fill_k(const int* __restrict__ ei) {
    int i = blockIdx.x * blockDim.x + threadIdx.x;   // 4 edges per thread
    if (i < N_EDGES / 4) {
        int4 s = ((const int4*)ei)[i];
        int4 d = ((const int4*)(ei + N_EDGES))[i];
        int4 r = ((const int4*)g_rank)[i];
        g_col[g_rowptr[d.x] + r.x] = s.x;
        g_col[g_rowptr[d.y] + r.y] = s.y;
        g_col[g_rowptr[d.z] + r.z] = s.z;
        g_col[g_rowptr[d.w] + r.w] = s.w;
    }
    if (i < N_NODES / 4) ((int4*)g_cnt)[i] = make_int4(0, 0, 0, 0);
}

// ---------------------------------------------------------------- Layer 0 (fused)
// 8 lanes per node: gather-reduce xd (3ch), then each lane emits 8 channels of
// relu(aggx @ W0 + b0) into g_buf0.
__global__ void agg_x_gemm0_k(const float* __restrict__ W0, const float* __restrict__ b0) {
    __shared__ float Ws[3 * HID];
    __shared__ float Bs[HID];
    int t = threadIdx.x;
    if (t < 3 * HID) Ws[t] = W0[t];
    if (t < HID) Bs[t] = b0[t];
    __syncthreads();
    int node = (blockIdx.x * blockDim.x + t) >> 3;
    int l8   = t & 7;
    if (node >= N_NODES) return;
    int s = g_rowptr[node];
    int e = g_rowptr[node + 1];
    float ax = 0.f, ay = 0.f, az = 0.f;
    if (l8 == 0) { float4 v = g_xd[node]; ax = v.x; ay = v.y; az = v.z; }
    for (int idx = s + l8; idx < e; idx += 8) {
        float4 v = g_xd[g_col[idx]];
        ax += v.x; ay += v.y; az += v.z;
    }
#pragma unroll
    for (int off = 1; off < 8; off <<= 1) {
        ax += __shfl_xor_sync(0xffffffffu, ax, off);
        ay += __shfl_xor_sync(0xffffffffu, ay, off);
        az += __shfl_xor_sync(0xffffffffu, az, off);
    }
    float di = g_dinv[node];
    ax *= di; ay *= di; az *= di;
    int c0 = l8 * 8;
    float o[8];
#pragma unroll
    for (int q = 0; q < 8; q++) {
        int c = c0 + q;
        o[q] = fmaxf(fmaf(ax, Ws[c], fmaf(ay, Ws[HID + c], fmaf(az, Ws[2 * HID + c], Bs[c]))), 0.f);
    }
    *(float4*)&g_buf0[node * HID + c0]     = make_float4(o[0], o[1], o[2], o[3]);
    *(float4*)&g_buf0[node * HID + c0 + 4] = make_float4(o[4], o[5], o[6], o[7]);
}

// ---------------------------------------------------------------- GEMM 64x64
// g_gath[r] = bf16( (g_buf0 @ W)[r] * dinv[r] )
__global__ void gemm64_k(const float* __restrict__ W) {
    __shared__ float hs[64 * 65];
    __shared__ float ws[64 * 64];
    int t  = threadIdx.x;
    int rb = blockIdx.x * 64;
    {
        const float4* Wv = (const float4*)W;
        float4* wv = (float4*)ws;
#pragma unroll
        for (int q = 0; q < 4; q++) { int i = t + q * 256; wv[i] = Wv[i]; }
    }
#pragma unroll
    for (int q = 0; q < 4; q++) {
        int i = t + q * 256;
        int r = i >> 4, kq = (i & 15) << 2;
        float4 v = make_float4(0.f, 0.f, 0.f, 0.f);
        if (rb + r < N_NODES) v = *(const float4*)&g_buf0[(rb + r) * HID + kq];
        hs[r * 65 + kq]     = v.x;
        hs[r * 65 + kq + 1] = v.y;
        hs[r * 65 + kq + 2] = v.z;
        hs[r * 65 + kq + 3] = v.w;
    }
    __syncthreads();
    int tx = t & 15, ty = t >> 4;
    int c0 = tx * 4, r0 = ty * 4;
    float acc[4][4] = {};
#pragma unroll
    for (int k = 0; k < 64; k++) {
        float4 b = *(const float4*)&ws[k * 64 + c0];
        float a0 = hs[(r0 + 0) * 65 + k];
        float a1 = hs[(r0 + 1) * 65 + k];
        float a2 = hs[(r0 + 2) * 65 + k];
        float a3 = hs[(r0 + 3) * 65 + k];
        acc[0][0] += a0 * b.x; acc[0][1] += a0 * b.y; acc[0][2] += a0 * b.z; acc[0][3] += a0 * b.w;
        acc[1][0] += a1 * b.x; acc[1][1] += a1 * b.y; acc[1][2] += a1 * b.z; acc[1][3] += a1 * b.w;
        acc[2][0] += a2 * b.x; acc[2][1] += a2 * b.y; acc[2][2] += a2 * b.z; acc[2][3] += a2 * b.w;
        acc[3][0] += a3 * b.x; acc[3][1] += a3 * b.y; acc[3][2] += a3 * b.z; acc[3][3] += a3 * b.w;
    }
#pragma unroll
    for (int i = 0; i < 4; i++) {
        int r = rb + r0 + i;
        if (r < N_NODES) {
            float di = g_dinv[r];
            __nv_bfloat162 p0 = __floats2bfloat162_rn(acc[i][0] * di, acc[i][1] * di);
            __nv_bfloat162 p1 = __floats2bfloat162_rn(acc[i][2] * di, acc[i][3] * di);
            uint2 pk;
            pk.x = *(unsigned int*)&p0;
            pk.y = *(unsigned int*)&p1;
            *(uint2*)&g_gath[r * HID + c0] = pk;
        }
    }
}

// ---------------------------------------------------------------- Aggregation
// One warp per dst node; 4 groups x 8 lanes, bf16 rows, fp32 accumulate.
// 16 edges per unrolled step -> 4 independent 16B loads in flight per lane.
__global__ void agg_k(const float* __restrict__ bias) {
    int w    = (blockIdx.x * blockDim.x + threadIdx.x) >> 5;
    int lane = threadIdx.x & 31;
    if (w >= N_NODES) return;
    int grp = lane >> 3;          // 0..3
    int l8  = lane & 7;           // 0..7
    int ch0 = l8 * 8;             // first of 8 channels for this lane
    int s = g_rowptr[w];
    int e = g_rowptr[w + 1];

    float2 a0 = make_float2(0.f, 0.f), a1 = a0, a2 = a0, a3 = a0;

#define ACC_ROW(SRC)                                                          \
    {                                                                         \
        uint4 pk = *(const uint4*)&g_gath[(SRC) * HID + ch0];                 \
        float2 f0 = __bfloat1622float2(*(__nv_bfloat162*)&pk.x);              \
        float2 f1 = __bfloat1622float2(*(__nv_bfloat162*)&pk.y);              \
        float2 f2 = __bfloat1622float2(*(__nv_bfloat162*)&pk.z);              \
        float2 f3 = __bfloat1622float2(*(__nv_bfloat162*)&pk.w);              \
        a0.x += f0.x; a0.y += f0.y; a1.x += f1.x; a1.y += f1.y;               \
        a2.x += f2.x; a2.y += f2.y; a3.x += f3.x; a3.y += f3.y;               \
    }

    for (int base = s; base < e; base += 32) {
        int idx = base + lane;
        int cv = (idx < e) ? g_col[idx] : 0;
        int m = e - base;
        if (m > 32) m = 32;
        int j = 0;
        for (; j + 16 <= m; j += 16) {
            int s0 = __shfl_sync(0xffffffffu, cv, j + grp);
            int s1 = __shfl_sync(0xffffffffu, cv, j + 4 + grp);
            int s2 = __shfl_sync(0xffffffffu, cv, j + 8 + grp);
            int s3 = __shfl_sync(0xffffffffu, cv, j + 12 + grp);
            ACC_ROW(s0);
            ACC_ROW(s1);
            ACC_ROW(s2);
            ACC_ROW(s3);
        }
        for (; j + 4 <= m; j += 4) {
            int s0 = __shfl_sync(0xffffffffu, cv, j + grp);
            ACC_ROW(s0);
        }
        if (j < m) {
            int jj = j + grp;
            int sj = __shfl_sync(0xffffffffu, cv, (jj < m) ? jj : (m - 1));
            if (jj < m) ACC_ROW(sj);
        }
    }
#undef ACC_ROW

#pragma unroll
    for (int off = 8; off <= 16; off <<= 1) {
        a0.x += __shfl_xor_sync(0xffffffffu, a0.x, off);
        a0.y += __shfl_xor_sync(0xffffffffu, a0.y, off);
        a1.x += __shfl_xor_sync(0xffffffffu, a1.x, off);
        a1.y += __shfl_xor_sync(0xffffffffu, a1.y, off);
        a2.x += __shfl_xor_sync(0xffffffffu, a2.x, off);
        a2.y += __shfl_xor_sync(0xffffffffu, a2.y, off);
        a3.x += __shfl_xor_sync(0xffffffffu, a3.x, off);
        a3.y += __shfl_xor_sync(0xffffffffu, a3.y, off);
    }

    if (grp == 0) {
        uint4 pk = *(const uint4*)&g_gath[w * HID + ch0];   // self loop
        float2 f0 = __bfloat1622float2(*(__nv_bfloat162*)&pk.x);
        float2 f1 = __bfloat1622float2(*(__nv_bfloat162*)&pk.y);
        float2 f2 = __bfloat1622float2(*(__nv_bfloat162*)&pk.z);
        float2 f3 = __bfloat1622float2(*(__nv_bfloat162*)&pk.w);
        a0.x += f0.x; a0.y += f0.y; a1.x += f1.x; a1.y += f1.y;
        a2.x += f2.x; a2.y += f2.y; a3.x += f3.x; a3.y += f3.y;

        float di = g_dinv[w];
        float4 bA = *(const float4*)&bias[ch0];
        float4 bB = *(const float4*)&bias[ch0 + 4];
        float4 r0, r1;
        r0.x = fmaxf(fmaf(a0.x, di, bA.x), 0.f);
        r0.y = fmaxf(fmaf(a0.y, di, bA.y), 0.f);
        r0.z = fmaxf(fmaf(a1.x, di, bA.z), 0.f);
        r0.w = fmaxf(fmaf(a1.y, di, bA.w), 0.f);
        r1.x = fmaxf(fmaf(a2.x, di, bB.x), 0.f);
        r1.y = fmaxf(fmaf(a2.y, di, bB.y), 0.f);
        r1.z = fmaxf(fmaf(a3.x, di, bB.z), 0.f);
        r1.w = fmaxf(fmaf(a3.y, di, bB.w), 0.f);
        *(float4*)&g_buf0[w * HID + ch0]     = r0;
        *(float4*)&g_buf0[w * HID + ch0 + 4] = r1;
    }
}

// ---------------------------------------------------------------- Pool + head (fused)
__global__ void poolfc_k(const int* __restrict__ batch,
                         const float* __restrict__ fc1w, const float* __restrict__ fc1b,
                         const float* __restrict__ fc2w, const float* __restrict__ fc2b,
                         float* __restrict__ out) {
    int g = blockIdx.x, t = threadIdx.x;   // 128 blocks x 256 thr
    __shared__ int lo_s, hi_s;
    if (t == 0) {
        int lo = 0, hi = N_NODES;
        while (lo < hi) { int m = (lo + hi) >> 1; if (batch[m] < g) lo = m + 1; else hi = m; }
        lo_s = lo;
        int lo2 = lo, hi2 = N_NODES;
        while (lo2 < hi2) { int m = (lo2 + hi2) >> 1; if (batch[m] < g + 1) lo2 = m + 1; else hi2 = m; }
        hi_s = lo2;
    }
    __syncthreads();
    int lo = lo_s, hi = hi_s;
    int c = t & 63, rg = t >> 6;
    float acc = 0.f;
    for (int r = lo + rg; r < hi; r += 4) acc += g_buf0[r * HID + c];
    __shared__ float sh[256];
    __shared__ float p[64];
    sh[t] = acc;
    __syncthreads();
    if (t < 64) {
        float s = sh[t] + sh[t + 64] + sh[t + 128] + sh[t + 192];
        float cntf = (float)(hi - lo);
        if (cntf < 1.f) cntf = 1.f;
        p[t] = s / cntf;
    }
    __syncthreads();
    float v = 0.f;
    if (t < DENSE) {
        float a = fc1b[t];
#pragma unroll
        for (int k = 0; k < 64; k++) a = fmaf(p[k], fc1w[k * DENSE + t], a);
        v = fmaxf(a, 0.f) * fc2w[t];
    }
    __syncthreads();
    sh[t] = v;
    __syncthreads();
    if (t < 64) sh[t] += sh[t + 64];
    __syncthreads();
    if (t < 32) {
        float s = sh[t] + sh[t + 32];
#pragma unroll
        for (int off = 16; off; off >>= 1) s += __shfl_down_sync(0xffffffffu, s, off);
        if (t == 0) out[g] = s + fc2b[0];
    }
}

// ---------------------------------------------------------------- launch
extern "C" void kernel_launch(void* const* d_in, const int* in_sizes, int n_in,
                              void* d_out, int out_size) {
    const float* x     = (const float*)d_in[0];
    const int*   ei    = (const int*)d_in[1];
    const int*   batch = (const int*)d_in[2];
    const float* W0    = (const float*)d_in[3];
    const float* b0    = (const float*)d_in[4];
    const float* W1    = (const float*)d_in[5];
    const float* b1    = (const float*)d_in[6];
    const float* W2    = (const float*)d_in[7];
    const float* b2    = (const float*)d_in[8];
    const float* fc1w  = (const float*)d_in[9];
    const float* fc1b  = (const float*)d_in[10];
    const float* fc2w  = (const float*)d_in[11];
    const float* fc2b  = (const float*)d_in[12];
    float* out = (float*)d_out;

    // CSR build (g_cnt enters zeroed: zero-init at load, re-zeroed by fill_k)
    hist_k<<<(N_EDGES / 4 + 255) / 256, 256>>>(ei);
    scan1_k<<<NB, 1024>>>();
    scan3_k<<<(N_NODES + 255) / 256, 256>>>(x);
    fill_k<<<(N_EDGES / 4 + 255) / 256, 256>>>(ei);

    const int AGG_BLOCKS  = (N_NODES * 32 + 255) / 256;
    const int GEMM_BLOCKS = (N_NODES + 63) / 64;

    // Layer 0 (fused 3-ch aggregate + dense)
    agg_x_gemm0_k<<<(N_NODES * 8 + 255) / 256, 256>>>(W0, b0);
    // Layer 1
    gemm64_k<<<GEMM_BLOCKS, 256>>>(W1);
    agg_k<<<AGG_BLOCKS, 256>>>(b1);
    // Layer 2
    gemm64_k<<<GEMM_BLOCKS, 256>>>(W2);
    agg_k<<<AGG_BLOCKS, 256>>>(b2);

    // Pool + head
    poolfc_k<<<NGRAPH, 256>>>(batch, fc1w, fc1b, fc2w, fc2b, out);
}

// round 8
// speedup vs baseline: 1.1125x; 1.1125x over previous
#include <cuda_runtime.h>
#include <cuda_bf16.h>
#include <cstdint>

#define N_NODES 100000
#define N_EDGES 1600000
#define HID 64
#define NGRAPH 128
#define DENSE 128
#define SCAN_BLK 4096
#define NB ((N_NODES + SCAN_BLK - 1) / SCAN_BLK)   // 25

// Scratch
__device__ float           g_buf0[N_NODES * HID];  // fp32 h (layer-2 agg out, pool input)
__device__ __nv_bfloat16   g_hb[N_NODES * HID];    // bf16 h (gemm input)
__device__ __nv_bfloat16   g_gath[N_NODES * HID];  // (h@W)*dinv, bf16 gather buffer
__device__ int    g_cnt[N_NODES];                  // zeroed at end of fill_k each call
__device__ int    g_rowptr[N_NODES + 1];
__device__ int    g_cursor[N_NODES];
__device__ int    g_col[N_EDGES];
__device__ float  g_dinv[N_NODES];
__device__ float4 g_xd[N_NODES];                   // x * dinv[src], padded
__device__ int    g_bsum[NB];

// ---------------------------------------------------------------- CSR build
// Fire-and-forget histogram (REDG).
__global__ void hist_k(const int* __restrict__ ei) {
    int i = blockIdx.x * blockDim.x + threadIdx.x;   // 4 edges per thread
    if (i < N_EDGES / 4) {
        int4 d = ((const int4*)(ei + N_EDGES))[i];
        atomicAdd(&g_cnt[d.x], 1);
        atomicAdd(&g_cnt[d.y], 1);
        atomicAdd(&g_cnt[d.z], 1);
        atomicAdd(&g_cnt[d.w], 1);
    }
}

// Per-block local exclusive scan; also computes dinv and xd = x*dinv.
__global__ void scan1_k(const float* __restrict__ x) {
    __shared__ int sh[1024];
    int tid = threadIdx.x;
    int base = blockIdx.x * SCAN_BLK;
    int v[4];
    int local = 0;
#pragma unroll
    for (int q = 0; q < 4; q++) {
        int i = base + tid * 4 + q;
        v[q] = (i < N_NODES) ? g_cnt[i] : 0;
        local += v[q];
    }
    sh[tid] = local;
    for (int off = 1; off < 1024; off <<= 1) {
        __syncthreads();
        int t = (tid >= off) ? sh[tid - off] : 0;
        __syncthreads();
        sh[tid] += t;
    }
    __syncthreads();
    int run = sh[tid] - local;
#pragma unroll
    for (int q = 0; q < 4; q++) {
        int i = base + tid * 4 + q;
        if (i < N_NODES) {
            g_rowptr[i] = run; run += v[q];
            float di = rsqrtf((float)(v[q] + 1));   // +1 self loop
            g_dinv[i] = di;
            float x0 = x[i * 3 + 0], x1 = x[i * 3 + 1], x2 = x[i * 3 + 2];
            g_xd[i] = make_float4(x0 * di, x1 * di, x2 * di, 0.f);
        }
    }
    if (tid == 1023) g_bsum[blockIdx.x] = sh[1023];
}

// Add block offsets (redundant warp scan over g_bsum); init cursor.
__global__ void scan3_k() {
    __shared__ int off_s;
    __shared__ int tot_s;
    int t = threadIdx.x;
    if (t < 32) {
        int myblk = (blockIdx.x * blockDim.x) / SCAN_BLK;
        int v = (t < NB) ? g_bsum[t] : 0;
        int pre = (t < myblk) ? v : 0;
        int tot = v;
#pragma unroll
        for (int o = 16; o; o >>= 1) {
            pre += __shfl_xor_sync(0xffffffffu, pre, o);
            tot += __shfl_xor_sync(0xffffffffu, tot, o);
        }
        if (t == 0) { off_s = pre; tot_s = tot; }
    }
    __syncthreads();
    int i = blockIdx.x * blockDim.x + t;
    if (i < N_NODES) {
        int r = g_rowptr[i] + off_s;
        g_rowptr[i] = r;
        g_cursor[i] = r;
    }
    if (blockIdx.x == 0 && t == 0) g_rowptr[N_NODES] = tot_s;
}

// Cursor-based fill; re-zeroes g_cnt at the tail (scan1 was the last reader).
__global__ void fill_k(const int* __restrict__ ei) {
    int i = blockIdx.x * blockDim.x + threadIdx.x;   // 4 edges per thread
    if (i < N_EDGES / 4) {
        int4 s = ((const int4*)ei)[i];
        int4 d = ((const int4*)(ei + N_EDGES))[i];
        g_col[atomicAdd(&g_cursor[d.x], 1)] = s.x;
        g_col[atomicAdd(&g_cursor[d.y], 1)] = s.y;
        g_col[atomicAdd(&g_cursor[d.z], 1)] = s.z;
        g_col[atomicAdd(&g_cursor[d.w], 1)] = s.w;
    }
    if (i < N_NODES / 4) ((int4*)g_cnt)[i] = make_int4(0, 0, 0, 0);
}

// ---------------------------------------------------------------- Layer 0 (fused)
// 8 lanes per node: gather-reduce xd (3ch), then emit bf16 relu(aggx@W0+b0).
__global__ void agg_x_gemm0_k(const float* __restrict__ W0, const float* __restrict__ b0) {
    __shared__ float Ws[3 * HID];
    __shared__ float Bs[HID];
    int t = threadIdx.x;
    if (t < 3 * HID) Ws[t] = W0[t];
    if (t < HID) Bs[t] = b0[t];
    __syncthreads();
    int node = (blockIdx.x * blockDim.x + t) >> 3;
    int l8   = t & 7;
    if (node >= N_NODES) return;
    int s = g_rowptr[node];
    int e = g_rowptr[node + 1];
    float ax = 0.f, ay = 0.f, az = 0.f;
    if (l8 == 0) { float4 v = g_xd[node]; ax = v.x; ay = v.y; az = v.z; }
    for (int idx = s + l8; idx < e; idx += 8) {
        float4 v = g_xd[g_col[idx]];
        ax += v.x; ay += v.y; az += v.z;
    }
#pragma unroll
    for (int off = 1; off < 8; off <<= 1) {
        ax += __shfl_xor_sync(0xffffffffu, ax, off);
        ay += __shfl_xor_sync(0xffffffffu, ay, off);
        az += __shfl_xor_sync(0xffffffffu, az, off);
    }
    float di = g_dinv[node];
    ax *= di; ay *= di; az *= di;
    int c0 = l8 * 8;
    float o[8];
#pragma unroll
    for (int q = 0; q < 8; q++) {
        int c = c0 + q;
        o[q] = fmaxf(fmaf(ax, Ws[c], fmaf(ay, Ws[HID + c], fmaf(az, Ws[2 * HID + c], Bs[c]))), 0.f);
    }
    __nv_bfloat162 p0 = __floats2bfloat162_rn(o[0], o[1]);
    __nv_bfloat162 p1 = __floats2bfloat162_rn(o[2], o[3]);
    __nv_bfloat162 p2 = __floats2bfloat162_rn(o[4], o[5]);
    __nv_bfloat162 p3 = __floats2bfloat162_rn(o[6], o[7]);
    uint4 pk;
    pk.x = *(uint32_t*)&p0; pk.y = *(uint32_t*)&p1;
    pk.z = *(uint32_t*)&p2; pk.w = *(uint32_t*)&p3;
    *(uint4*)&g_hb[node * HID + c0] = pk;
}

// ---------------------------------------------------------------- GEMM (tensor core)
// g_gath[r] = bf16( (hb @ W)[r] * dinv[r] ), hb bf16, W fp32->bf16, fp32 accum.
// 128 rows per block, 8 warps, each warp 16 rows. mma.m16n8k16.
#define AS_LD 72   // bf16 stride (64 + 8 pad)
__global__ void gemm64_k(const float* __restrict__ W) {
    __shared__ __nv_bfloat16 As[128 * AS_LD];
    __shared__ __nv_bfloat16 Wsm[64 * AS_LD];
    int t = threadIdx.x;
    int warp = t >> 5, lane = t & 31;
    int rb = blockIdx.x * 128;

    // Load + convert W (4096 elems, 16/thread)
#pragma unroll
    for (int q = 0; q < 16; q++) {
        int i = t + q * 256;
        int r = i >> 6, c = i & 63;
        Wsm[r * AS_LD + c] = __float2bfloat16(W[i]);
    }
    // Load A tile: 128 rows x 64 bf16 = 1024 uint4 (4/thread)
#pragma unroll
    for (int q = 0; q < 4; q++) {
        int i = t + q * 256;
        int r = i >> 3, seg = i & 7;
        uint4 v = make_uint4(0, 0, 0, 0);
        if (rb + r < N_NODES) v = ((const uint4*)&g_hb[(rb + r) * HID])[seg];
        *(uint4*)&As[r * AS_LD + seg * 8] = v;
    }
    __syncthreads();

    int wrow = warp * 16;
    float acc[8][4];
#pragma unroll
    for (int nb = 0; nb < 8; nb++)
#pragma unroll
        for (int q = 0; q < 4; q++) acc[nb][q] = 0.f;

#pragma unroll
    for (int ks = 0; ks < 4; ks++) {
        uint32_t a0, a1, a2, a3;
        {
            const __nv_bfloat16* ap = &As[(wrow + (lane & 15)) * AS_LD + ks * 16 + (lane >> 4) * 8];
            uint32_t addr = (uint32_t)__cvta_generic_to_shared(ap);
            asm volatile("ldmatrix.sync.aligned.m8n8.x4.shared.b16 {%0,%1,%2,%3}, [%4];"
                         : "=r"(a0), "=r"(a1), "=r"(a2), "=r"(a3) : "r"(addr));
        }
#pragma unroll
        for (int nb = 0; nb < 8; nb++) {
            uint32_t b0, b1;
            const __nv_bfloat16* bp = &Wsm[(ks * 16 + (lane & 15)) * AS_LD + nb * 8];
            uint32_t baddr = (uint32_t)__cvta_generic_to_shared(bp);
            asm volatile("ldmatrix.sync.aligned.m8n8.x2.trans.shared.b16 {%0,%1}, [%2];"
                         : "=r"(b0), "=r"(b1) : "r"(baddr));
            asm volatile(
                "mma.sync.aligned.m16n8k16.row.col.f32.bf16.bf16.f32 "
                "{%0,%1,%2,%3},{%4,%5,%6,%7},{%8,%9},{%0,%1,%2,%3};"
                : "+f"(acc[nb][0]), "+f"(acc[nb][1]), "+f"(acc[nb][2]), "+f"(acc[nb][3])
                : "r"(a0), "r"(a1), "r"(a2), "r"(a3), "r"(b0), "r"(b1));
        }
    }

    // Epilogue: row0 = rb+wrow+(lane>>2), row1 = row0+8; cols nb*8+(lane&3)*2
    int r0 = rb + wrow + (lane >> 2);
    int r1 = r0 + 8;
    float di0 = (r0 < N_NODES) ? g_dinv[r0] : 0.f;
    float di1 = (r1 < N_NODES) ? g_dinv[r1] : 0.f;
    int cb = (lane & 3) * 2;
#pragma unroll
    for (int nb = 0; nb < 8; nb++) {
        int c = nb * 8 + cb;
        if (r0 < N_NODES) {
            __nv_bfloat162 p = __floats2bfloat162_rn(acc[nb][0] * di0, acc[nb][1] * di0);
            *(uint32_t*)&g_gath[r0 * HID + c] = *(uint32_t*)&p;
        }
        if (r1 < N_NODES) {
            __nv_bfloat162 p = __floats2bfloat162_rn(acc[nb][2] * di1, acc[nb][3] * di1);
            *(uint32_t*)&g_gath[r1 * HID + c] = *(uint32_t*)&p;
        }
    }
}

// ---------------------------------------------------------------- Aggregation
// One warp per dst node; 4 groups x 8 lanes, bf16 rows, fp32 accumulate.
// OUT_BF16: write bf16 g_hb (next gemm input); else fp32 g_buf0 (pool input).
template <bool OUT_BF16>
__global__ void agg_k(const float* __restrict__ bias) {
    int w    = (blockIdx.x * blockDim.x + threadIdx.x) >> 5;
    int lane = threadIdx.x & 31;
    if (w >= N_NODES) return;
    int grp = lane >> 3;
    int l8  = lane & 7;
    int ch0 = l8 * 8;
    int s = g_rowptr[w];
    int e = g_rowptr[w + 1];

    float2 a0 = make_float2(0.f, 0.f), a1 = a0, a2 = a0, a3 = a0;

#define ACC_ROW(SRC)                                                          \
    {                                                                         \
        uint4 pk = *(const uint4*)&g_gath[(SRC) * HID + ch0];                 \
        float2 f0 = __bfloat1622float2(*(__nv_bfloat162*)&pk.x);              \
        float2 f1 = __bfloat1622float2(*(__nv_bfloat162*)&pk.y);              \
        float2 f2 = __bfloat1622float2(*(__nv_bfloat162*)&pk.z);              \
        float2 f3 = __bfloat1622float2(*(__nv_bfloat162*)&pk.w);              \
        a0.x += f0.x; a0.y += f0.y; a1.x += f1.x; a1.y += f1.y;               \
        a2.x += f2.x; a2.y += f2.y; a3.x += f3.x; a3.y += f3.y;               \
    }

    for (int base = s; base < e; base += 32) {
        int idx = base + lane;
        int cv = (idx < e) ? g_col[idx] : 0;
        int m = e - base;
        if (m > 32) m = 32;
        int j = 0;
        for (; j + 16 <= m; j += 16) {
            int s0 = __shfl_sync(0xffffffffu, cv, j + grp);
            int s1 = __shfl_sync(0xffffffffu, cv, j + 4 + grp);
            int s2 = __shfl_sync(0xffffffffu, cv, j + 8 + grp);
            int s3 = __shfl_sync(0xffffffffu, cv, j + 12 + grp);
            ACC_ROW(s0); ACC_ROW(s1); ACC_ROW(s2); ACC_ROW(s3);
        }
        for (; j + 4 <= m; j += 4) {
            int s0 = __shfl_sync(0xffffffffu, cv, j + grp);
            ACC_ROW(s0);
        }
        if (j < m) {
            int jj = j + grp;
            int sj = __shfl_sync(0xffffffffu, cv, (jj < m) ? jj : (m - 1));
            if (jj < m) ACC_ROW(sj);
        }
    }
#undef ACC_ROW

#pragma unroll
    for (int off = 8; off <= 16; off <<= 1) {
        a0.x += __shfl_xor_sync(0xffffffffu, a0.x, off);
        a0.y += __shfl_xor_sync(0xffffffffu, a0.y, off);
        a1.x += __shfl_xor_sync(0xffffffffu, a1.x, off);
        a1.y += __shfl_xor_sync(0xffffffffu, a1.y, off);
        a2.x += __shfl_xor_sync(0xffffffffu, a2.x, off);
        a2.y += __shfl_xor_sync(0xffffffffu, a2.y, off);
        a3.x += __shfl_xor_sync(0xffffffffu, a3.x, off);
        a3.y += __shfl_xor_sync(0xffffffffu, a3.y, off);
    }

    if (grp == 0) {
        uint4 pk = *(const uint4*)&g_gath[w * HID + ch0];   // self loop
        float2 f0 = __bfloat1622float2(*(__nv_bfloat162*)&pk.x);
        float2 f1 = __bfloat1622float2(*(__nv_bfloat162*)&pk.y);
        float2 f2 = __bfloat1622float2(*(__nv_bfloat162*)&pk.z);
        float2 f3 = __bfloat1622float2(*(__nv_bfloat162*)&pk.w);
        a0.x += f0.x; a0.y += f0.y; a1.x += f1.x; a1.y += f1.y;
        a2.x += f2.x; a2.y += f2.y; a3.x += f3.x; a3.y += f3.y;

        float di = g_dinv[w];
        float4 bA = *(const float4*)&bias[ch0];
        float4 bB = *(const float4*)&bias[ch0 + 4];
        float o0 = fmaxf(fmaf(a0.x, di, bA.x), 0.f);
        float o1 = fmaxf(fmaf(a0.y, di, bA.y), 0.f);
        float o2 = fmaxf(fmaf(a1.x, di, bA.z), 0.f);
        float o3 = fmaxf(fmaf(a1.y, di, bA.w), 0.f);
        float o4 = fmaxf(fmaf(a2.x, di, bB.x), 0.f);
        float o5 = fmaxf(fmaf(a2.y, di, bB.y), 0.f);
        float o6 = fmaxf(fmaf(a3.x, di, bB.z), 0.f);
        float o7 = fmaxf(fmaf(a3.y, di, bB.w), 0.f);
        if (OUT_BF16) {
            __nv_bfloat162 p0 = __floats2bfloat162_rn(o0, o1);
            __nv_bfloat162 p1 = __floats2bfloat162_rn(o2, o3);
            __nv_bfloat162 p2 = __floats2bfloat162_rn(o4, o5);
            __nv_bfloat162 p3 = __floats2bfloat162_rn(o6, o7);
            uint4 pko;
            pko.x = *(uint32_t*)&p0; pko.y = *(uint32_t*)&p1;
            pko.z = *(uint32_t*)&p2; pko.w = *(uint32_t*)&p3;
            *(uint4*)&g_hb[w * HID + ch0] = pko;
        } else {
            *(float4*)&g_buf0[w * HID + ch0]     = make_float4(o0, o1, o2, o3);
            *(float4*)&g_buf0[w * HID + ch0 + 4] = make_float4(o4, o5, o6, o7);
        }
    }
}

// ---------------------------------------------------------------- Pool + head (fused)
__global__ void poolfc_k(const int* __restrict__ batch,
                         const float* __restrict__ fc1w, const float* __restrict__ fc1b,
                         const float* __restrict__ fc2w, const float* __restrict__ fc2b,
                         float* __restrict__ out) {
    int g = blockIdx.x, t = threadIdx.x;   // 128 blocks x 256 thr
    __shared__ int lo_s, hi_s;
    if (t == 0) {
        int lo = 0, hi = N_NODES;
        while (lo < hi) { int m = (lo + hi) >> 1; if (batch[m] < g) lo = m + 1; else hi = m; }
        lo_s = lo;
        int lo2 = lo, hi2 = N_NODES;
        while (lo2 < hi2) { int m = (lo2 + hi2) >> 1; if (batch[m] < g + 1) lo2 = m + 1; else hi2 = m; }
        hi_s = lo2;
    }
    __syncthreads();
    int lo = lo_s, hi = hi_s;
    int c = t & 63, rg = t >> 6;
    float acc = 0.f;
    for (int r = lo + rg; r < hi; r += 4) acc += g_buf0[r * HID + c];
    __shared__ float sh[256];
    __shared__ float p[64];
    sh[t] = acc;
    __syncthreads();
    if (t < 64) {
        float s = sh[t] + sh[t + 64] + sh[t + 128] + sh[t + 192];
        float cntf = (float)(hi - lo);
        if (cntf < 1.f) cntf = 1.f;
        p[t] = s / cntf;
    }
    __syncthreads();
    float v = 0.f;
    if (t < DENSE) {
        float a = fc1b[t];
#pragma unroll
        for (int k = 0; k < 64; k++) a = fmaf(p[k], fc1w[k * DENSE + t], a);
        v = fmaxf(a, 0.f) * fc2w[t];
    }
    __syncthreads();
    sh[t] = v;
    __syncthreads();
    if (t < 64) sh[t] += sh[t + 64];
    __syncthreads();
    if (t < 32) {
        float s = sh[t] + sh[t + 32];
#pragma unroll
        for (int off = 16; off; off >>= 1) s += __shfl_down_sync(0xffffffffu, s, off);
        if (t == 0) out[g] = s + fc2b[0];
    }
}

// ---------------------------------------------------------------- launch
extern "C" void kernel_launch(void* const* d_in, const int* in_sizes, int n_in,
                              void* d_out, int out_size) {
    const float* x     = (const float*)d_in[0];
    const int*   ei    = (const int*)d_in[1];
    const int*   batch = (const int*)d_in[2];
    const float* W0    = (const float*)d_in[3];
    const float* b0    = (const float*)d_in[4];
    const float* W1    = (const float*)d_in[5];
    const float* b1    = (const float*)d_in[6];
    const float* W2    = (const float*)d_in[7];
    const float* b2    = (const float*)d_in[8];
    const float* fc1w  = (const float*)d_in[9];
    const float* fc1b  = (const float*)d_in[10];
    const float* fc2w  = (const float*)d_in[11];
    const float* fc2b  = (const float*)d_in[12];
    float* out = (float*)d_out;

    // CSR build (g_cnt enters zeroed: zero-init at load, re-zeroed by fill_k)
    hist_k<<<(N_EDGES / 4 + 255) / 256, 256>>>(ei);
    scan1_k<<<NB, 1024>>>(x);
    scan3_k<<<(N_NODES + 255) / 256, 256>>>();
    fill_k<<<(N_EDGES / 4 + 255) / 256, 256>>>(ei);

    const int AGG_BLOCKS  = (N_NODES * 32 + 255) / 256;
    const int GEMM_BLOCKS = (N_NODES + 127) / 128;

    // Layer 0 (fused 3-ch aggregate + dense, bf16 out)
    agg_x_gemm0_k<<<(N_NODES * 8 + 255) / 256, 256>>>(W0, b0);
    // Layer 1
    gemm64_k<<<GEMM_BLOCKS, 256>>>(W1);
    agg_k<true><<<AGG_BLOCKS, 256>>>(b1);
    // Layer 2
    gemm64_k<<<GEMM_BLOCKS, 256>>>(W2);
    agg_k<false><<<AGG_BLOCKS, 256>>>(b2);

    // Pool + head
    poolfc_k<<<NGRAPH, 256>>>(batch, fc1w, fc1b, fc2w, fc2b, out);
}

// round 9
// speedup vs baseline: 1.1522x; 1.0357x over previous
#include <cuda_runtime.h>
#include <cuda_bf16.h>
#include <cstdint>

#define N_NODES 100000
#define N_EDGES 1600000
#define HID 64
#define NGRAPH 128
#define DENSE 128
#define SCAN_BLK 4096
#define NB ((N_NODES + SCAN_BLK - 1) / SCAN_BLK)   // 25

// Scratch
__device__ float           g_buf0[N_NODES * HID];  // fp32 h (layer-2 agg out, pool input)
__device__ __nv_bfloat16   g_hb[N_NODES * HID];    // bf16 h (gemm input)
__device__ __nv_bfloat16   g_gath[N_NODES * HID];  // (h@W)*dinv, bf16 gather buffer
__device__ int    g_cnt[N_NODES];                  // zeroed at end of fill_k each call
__device__ int    g_rowptr[N_NODES + 1];
__device__ int    g_cursor[N_NODES];
__device__ int    g_col[N_EDGES];
__device__ float  g_dinv[N_NODES];
__device__ float4 g_xd[N_NODES];                   // x * dinv[src], padded
__device__ int    g_bsum[NB];

// ---------------------------------------------------------------- CSR build
// Fire-and-forget histogram (REDG). 8 edges per thread.
__global__ void hist_k(const int* __restrict__ ei) {
    int i = blockIdx.x * blockDim.x + threadIdx.x;
    if (i < N_EDGES / 8) {
        int4 d0 = ((const int4*)(ei + N_EDGES))[i * 2];
        int4 d1 = ((const int4*)(ei + N_EDGES))[i * 2 + 1];
        atomicAdd(&g_cnt[d0.x], 1);
        atomicAdd(&g_cnt[d0.y], 1);
        atomicAdd(&g_cnt[d0.z], 1);
        atomicAdd(&g_cnt[d0.w], 1);
        atomicAdd(&g_cnt[d1.x], 1);
        atomicAdd(&g_cnt[d1.y], 1);
        atomicAdd(&g_cnt[d1.z], 1);
        atomicAdd(&g_cnt[d1.w], 1);
    }
}

// Per-block local exclusive scan; also computes dinv and xd = x*dinv.
__global__ void scan1_k(const float* __restrict__ x) {
    __shared__ int sh[1024];
    int tid = threadIdx.x;
    int base = blockIdx.x * SCAN_BLK;
    int v[4];
    int local = 0;
#pragma unroll
    for (int q = 0; q < 4; q++) {
        int i = base + tid * 4 + q;
        v[q] = (i < N_NODES) ? g_cnt[i] : 0;
        local += v[q];
    }
    sh[tid] = local;
    for (int off = 1; off < 1024; off <<= 1) {
        __syncthreads();
        int t = (tid >= off) ? sh[tid - off] : 0;
        __syncthreads();
        sh[tid] += t;
    }
    __syncthreads();
    int run = sh[tid] - local;
#pragma unroll
    for (int q = 0; q < 4; q++) {
        int i = base + tid * 4 + q;
        if (i < N_NODES) {
            g_rowptr[i] = run; run += v[q];
            float di = rsqrtf((float)(v[q] + 1));   // +1 self loop
            g_dinv[i] = di;
            float x0 = x[i * 3 + 0], x1 = x[i * 3 + 1], x2 = x[i * 3 + 2];
            g_xd[i] = make_float4(x0 * di, x1 * di, x2 * di, 0.f);
        }
    }
    if (tid == 1023) g_bsum[blockIdx.x] = sh[1023];
}

// Add block offsets (redundant warp scan over g_bsum); init cursor.
__global__ void scan3_k() {
    __shared__ int off_s;
    __shared__ int tot_s;
    int t = threadIdx.x;
    if (t < 32) {
        int myblk = (blockIdx.x * blockDim.x) / SCAN_BLK;
        int v = (t < NB) ? g_bsum[t] : 0;
        int pre = (t < myblk) ? v : 0;
        int tot = v;
#pragma unroll
        for (int o = 16; o; o >>= 1) {
            pre += __shfl_xor_sync(0xffffffffu, pre, o);
            tot += __shfl_xor_sync(0xffffffffu, tot, o);
        }
        if (t == 0) { off_s = pre; tot_s = tot; }
    }
    __syncthreads();
    int i = blockIdx.x * blockDim.x + t;
    if (i < N_NODES) {
        int r = g_rowptr[i] + off_s;
        g_rowptr[i] = r;
        g_cursor[i] = r;
    }
    if (blockIdx.x == 0 && t == 0) g_rowptr[N_NODES] = tot_s;
}

// Cursor-based fill, 8 edges per thread; re-zeroes g_cnt at the tail.
__global__ void fill_k(const int* __restrict__ ei) {
    int i = blockIdx.x * blockDim.x + threadIdx.x;
    if (i < N_EDGES / 8) {
        int4 s0 = ((const int4*)ei)[i * 2];
        int4 s1 = ((const int4*)ei)[i * 2 + 1];
        int4 d0 = ((const int4*)(ei + N_EDGES))[i * 2];
        int4 d1 = ((const int4*)(ei + N_EDGES))[i * 2 + 1];
        int p0 = atomicAdd(&g_cursor[d0.x], 1);
        int p1 = atomicAdd(&g_cursor[d0.y], 1);
        int p2 = atomicAdd(&g_cursor[d0.z], 1);
        int p3 = atomicAdd(&g_cursor[d0.w], 1);
        int p4 = atomicAdd(&g_cursor[d1.x], 1);
        int p5 = atomicAdd(&g_cursor[d1.y], 1);
        int p6 = atomicAdd(&g_cursor[d1.z], 1);
        int p7 = atomicAdd(&g_cursor[d1.w], 1);
        g_col[p0] = s0.x; g_col[p1] = s0.y; g_col[p2] = s0.z; g_col[p3] = s0.w;
        g_col[p4] = s1.x; g_col[p5] = s1.y; g_col[p6] = s1.z; g_col[p7] = s1.w;
    }
    if (i < N_NODES / 4) ((int4*)g_cnt)[i] = make_int4(0, 0, 0, 0);
}

// ---------------------------------------------------------------- Layer 0 (fused)
// 8 lanes per node: gather-reduce xd (3ch), then emit bf16 relu(aggx@W0+b0).
__global__ void agg_x_gemm0_k(const float* __restrict__ W0, const float* __restrict__ b0) {
    __shared__ float Ws[3 * HID];
    __shared__ float Bs[HID];
    int t = threadIdx.x;
    if (t < 3 * HID) Ws[t] = W0[t];
    if (t < HID) Bs[t] = b0[t];
    __syncthreads();
    int node = (blockIdx.x * blockDim.x + t) >> 3;
    int l8   = t & 7;
    if (node >= N_NODES) return;
    int s = g_rowptr[node];
    int e = g_rowptr[node + 1];
    float ax = 0.f, ay = 0.f, az = 0.f;
    if (l8 == 0) { float4 v = g_xd[node]; ax = v.x; ay = v.y; az = v.z; }
    for (int idx = s + l8; idx < e; idx += 8) {
        float4 v = g_xd[g_col[idx]];
        ax += v.x; ay += v.y; az += v.z;
    }
#pragma unroll
    for (int off = 1; off < 8; off <<= 1) {
        ax += __shfl_xor_sync(0xffffffffu, ax, off);
        ay += __shfl_xor_sync(0xffffffffu, ay, off);
        az += __shfl_xor_sync(0xffffffffu, az, off);
    }
    float di = g_dinv[node];
    ax *= di; ay *= di; az *= di;
    int c0 = l8 * 8;
    float o[8];
#pragma unroll
    for (int q = 0; q < 8; q++) {
        int c = c0 + q;
        o[q] = fmaxf(fmaf(ax, Ws[c], fmaf(ay, Ws[HID + c], fmaf(az, Ws[2 * HID + c], Bs[c]))), 0.f);
    }
    __nv_bfloat162 p0 = __floats2bfloat162_rn(o[0], o[1]);
    __nv_bfloat162 p1 = __floats2bfloat162_rn(o[2], o[3]);
    __nv_bfloat162 p2 = __floats2bfloat162_rn(o[4], o[5]);
    __nv_bfloat162 p3 = __floats2bfloat162_rn(o[6], o[7]);
    uint4 pk;
    pk.x = *(uint32_t*)&p0; pk.y = *(uint32_t*)&p1;
    pk.z = *(uint32_t*)&p2; pk.w = *(uint32_t*)&p3;
    *(uint4*)&g_hb[node * HID + c0] = pk;
}

// ---------------------------------------------------------------- GEMM (tensor core)
// g_gath[r] = bf16( (hb @ W)[r] * dinv[r] ), hb bf16, W fp32->bf16, fp32 accum.
#define AS_LD 72   // bf16 stride (64 + 8 pad)
__global__ void gemm64_k(const float* __restrict__ W) {
    __shared__ __nv_bfloat16 As[128 * AS_LD];
    __shared__ __nv_bfloat16 Wsm[64 * AS_LD];
    int t = threadIdx.x;
    int warp = t >> 5, lane = t & 31;
    int rb = blockIdx.x * 128;

#pragma unroll
    for (int q = 0; q < 16; q++) {
        int i = t + q * 256;
        int r = i >> 6, c = i & 63;
        Wsm[r * AS_LD + c] = __float2bfloat16(W[i]);
    }
#pragma unroll
    for (int q = 0; q < 4; q++) {
        int i = t + q * 256;
        int r = i >> 3, seg = i & 7;
        uint4 v = make_uint4(0, 0, 0, 0);
        if (rb + r < N_NODES) v = ((const uint4*)&g_hb[(rb + r) * HID])[seg];
        *(uint4*)&As[r * AS_LD + seg * 8] = v;
    }
    __syncthreads();

    int wrow = warp * 16;
    float acc[8][4];
#pragma unroll
    for (int nb = 0; nb < 8; nb++)
#pragma unroll
        for (int q = 0; q < 4; q++) acc[nb][q] = 0.f;

#pragma unroll
    for (int ks = 0; ks < 4; ks++) {
        uint32_t a0, a1, a2, a3;
        {
            const __nv_bfloat16* ap = &As[(wrow + (lane & 15)) * AS_LD + ks * 16 + (lane >> 4) * 8];
            uint32_t addr = (uint32_t)__cvta_generic_to_shared(ap);
            asm volatile("ldmatrix.sync.aligned.m8n8.x4.shared.b16 {%0,%1,%2,%3}, [%4];"
                         : "=r"(a0), "=r"(a1), "=r"(a2), "=r"(a3) : "r"(addr));
        }
#pragma unroll
        for (int nb = 0; nb < 8; nb++) {
            uint32_t b0, b1;
            const __nv_bfloat16* bp = &Wsm[(ks * 16 + (lane & 15)) * AS_LD + nb * 8];
            uint32_t baddr = (uint32_t)__cvta_generic_to_shared(bp);
            asm volatile("ldmatrix.sync.aligned.m8n8.x2.trans.shared.b16 {%0,%1}, [%2];"
                         : "=r"(b0), "=r"(b1) : "r"(baddr));
            asm volatile(
                "mma.sync.aligned.m16n8k16.row.col.f32.bf16.bf16.f32 "
                "{%0,%1,%2,%3},{%4,%5,%6,%7},{%8,%9},{%0,%1,%2,%3};"
                : "+f"(acc[nb][0]), "+f"(acc[nb][1]), "+f"(acc[nb][2]), "+f"(acc[nb][3])
                : "r"(a0), "r"(a1), "r"(a2), "r"(a3), "r"(b0), "r"(b1));
        }
    }

    int r0 = rb + wrow + (lane >> 2);
    int r1 = r0 + 8;
    float di0 = (r0 < N_NODES) ? g_dinv[r0] : 0.f;
    float di1 = (r1 < N_NODES) ? g_dinv[r1] : 0.f;
    int cb = (lane & 3) * 2;
#pragma unroll
    for (int nb = 0; nb < 8; nb++) {
        int c = nb * 8 + cb;
        if (r0 < N_NODES) {
            __nv_bfloat162 p = __floats2bfloat162_rn(acc[nb][0] * di0, acc[nb][1] * di0);
            *(uint32_t*)&g_gath[r0 * HID + c] = *(uint32_t*)&p;
        }
        if (r1 < N_NODES) {
            __nv_bfloat162 p = __floats2bfloat162_rn(acc[nb][2] * di1, acc[nb][3] * di1);
            *(uint32_t*)&g_gath[r1 * HID + c] = *(uint32_t*)&p;
        }
    }
}

// ---------------------------------------------------------------- Aggregation
// One warp per dst node; 4 groups x 8 lanes. Each group loads its own edge
// index directly (8-lane 4B broadcast = 1 sector), no shfl staging.
// bf16 rows, fp32 accumulate.
template <bool OUT_BF16>
__global__ void agg_k(const float* __restrict__ bias) {
    int w    = (blockIdx.x * blockDim.x + threadIdx.x) >> 5;
    int lane = threadIdx.x & 31;
    if (w >= N_NODES) return;
    int grp = lane >> 3;
    int l8  = lane & 7;
    int ch0 = l8 * 8;
    int s = g_rowptr[w];
    int e = g_rowptr[w + 1];

    float2 a0 = make_float2(0.f, 0.f), a1 = a0, a2 = a0, a3 = a0;

#define ACC_ROW(SRC)                                                          \
    {                                                                         \
        uint4 pk = *(const uint4*)&g_gath[(SRC) * HID + ch0];                 \
        float2 f0 = __bfloat1622float2(*(__nv_bfloat162*)&pk.x);              \
        float2 f1 = __bfloat1622float2(*(__nv_bfloat162*)&pk.y);              \
        float2 f2 = __bfloat1622float2(*(__nv_bfloat162*)&pk.z);              \
        float2 f3 = __bfloat1622float2(*(__nv_bfloat162*)&pk.w);              \
        a0.x += f0.x; a0.y += f0.y; a1.x += f1.x; a1.y += f1.y;               \
        a2.x += f2.x; a2.y += f2.y; a3.x += f3.x; a3.y += f3.y;               \
    }

    int idx = s + grp;
    for (; idx + 12 < e; idx += 16) {      // 4 edges per group in flight
        int s0 = g_col[idx];
        int s1 = g_col[idx + 4];
        int s2 = g_col[idx + 8];
        int s3 = g_col[idx + 12];
        ACC_ROW(s0); ACC_ROW(s1); ACC_ROW(s2); ACC_ROW(s3);
    }
    for (; idx < e; idx += 4) {
        int s0 = g_col[idx];
        ACC_ROW(s0);
    }
#undef ACC_ROW

#pragma unroll
    for (int off = 8; off <= 16; off <<= 1) {
        a0.x += __shfl_xor_sync(0xffffffffu, a0.x, off);
        a0.y += __shfl_xor_sync(0xffffffffu, a0.y, off);
        a1.x += __shfl_xor_sync(0xffffffffu, a1.x, off);
        a1.y += __shfl_xor_sync(0xffffffffu, a1.y, off);
        a2.x += __shfl_xor_sync(0xffffffffu, a2.x, off);
        a2.y += __shfl_xor_sync(0xffffffffu, a2.y, off);
        a3.x += __shfl_xor_sync(0xffffffffu, a3.x, off);
        a3.y += __shfl_xor_sync(0xffffffffu, a3.y, off);
    }

    if (grp == 0) {
        uint4 pk = *(const uint4*)&g_gath[w * HID + ch0];   // self loop
        float2 f0 = __bfloat1622float2(*(__nv_bfloat162*)&pk.x);
        float2 f1 = __bfloat1622float2(*(__nv_bfloat162*)&pk.y);
        float2 f2 = __bfloat1622float2(*(__nv_bfloat162*)&pk.z);
        float2 f3 = __bfloat1622float2(*(__nv_bfloat162*)&pk.w);
        a0.x += f0.x; a0.y += f0.y; a1.x += f1.x; a1.y += f1.y;
        a2.x += f2.x; a2.y += f2.y; a3.x += f3.x; a3.y += f3.y;

        float di = g_dinv[w];
        float4 bA = *(const float4*)&bias[ch0];
        float4 bB = *(const float4*)&bias[ch0 + 4];
        float o0 = fmaxf(fmaf(a0.x, di, bA.x), 0.f);
        float o1 = fmaxf(fmaf(a0.y, di, bA.y), 0.f);
        float o2 = fmaxf(fmaf(a1.x, di, bA.z), 0.f);
        float o3 = fmaxf(fmaf(a1.y, di, bA.w), 0.f);
        float o4 = fmaxf(fmaf(a2.x, di, bB.x), 0.f);
        float o5 = fmaxf(fmaf(a2.y, di, bB.y), 0.f);
        float o6 = fmaxf(fmaf(a3.x, di, bB.z), 0.f);
        float o7 = fmaxf(fmaf(a3.y, di, bB.w), 0.f);
        if (OUT_BF16) {
            __nv_bfloat162 p0 = __floats2bfloat162_rn(o0, o1);
            __nv_bfloat162 p1 = __floats2bfloat162_rn(o2, o3);
            __nv_bfloat162 p2 = __floats2bfloat162_rn(o4, o5);
            __nv_bfloat162 p3 = __floats2bfloat162_rn(o6, o7);
            uint4 pko;
            pko.x = *(uint32_t*)&p0; pko.y = *(uint32_t*)&p1;
            pko.z = *(uint32_t*)&p2; pko.w = *(uint32_t*)&p3;
            *(uint4*)&g_hb[w * HID + ch0] = pko;
        } else {
            *(float4*)&g_buf0[w * HID + ch0]     = make_float4(o0, o1, o2, o3);
            *(float4*)&g_buf0[w * HID + ch0 + 4] = make_float4(o4, o5, o6, o7);
        }
    }
}

// ---------------------------------------------------------------- Pool + head (fused)
__global__ void poolfc_k(const int* __restrict__ batch,
                         const float* __restrict__ fc1w, const float* __restrict__ fc1b,
                         const float* __restrict__ fc2w, const float* __restrict__ fc2b,
                         float* __restrict__ out) {
    int g = blockIdx.x, t = threadIdx.x;   // 128 blocks x 256 thr
    __shared__ int lo_s, hi_s;
    if (t == 0) {
        int lo = 0, hi = N_NODES;
        while (lo < hi) { int m = (lo + hi) >> 1; if (batch[m] < g) lo = m + 1; else hi = m; }
        lo_s = lo;
        int lo2 = lo, hi2 = N_NODES;
        while (lo2 < hi2) { int m = (lo2 + hi2) >> 1; if (batch[m] < g + 1) lo2 = m + 1; else hi2 = m; }
        hi_s = lo2;
    }
    __syncthreads();
    int lo = lo_s, hi = hi_s;
    int c = t & 63, rg = t >> 6;
    float acc = 0.f;
    for (int r = lo + rg; r < hi; r += 4) acc += g_buf0[r * HID + c];
    __shared__ float sh[256];
    __shared__ float p[64];
    sh[t] = acc;
    __syncthreads();
    if (t < 64) {
        float s = sh[t] + sh[t + 64] + sh[t + 128] + sh[t + 192];
        float cntf = (float)(hi - lo);
        if (cntf < 1.f) cntf = 1.f;
        p[t] = s / cntf;
    }
    __syncthreads();
    float v = 0.f;
    if (t < DENSE) {
        float a = fc1b[t];
#pragma unroll
        for (int k = 0; k < 64; k++) a = fmaf(p[k], fc1w[k * DENSE + t], a);
        v = fmaxf(a, 0.f) * fc2w[t];
    }
    __syncthreads();
    sh[t] = v;
    __syncthreads();
    if (t < 64) sh[t] += sh[t + 64];
    __syncthreads();
    if (t < 32) {
        float s = sh[t] + sh[t + 32];
#pragma unroll
        for (int off = 16; off; off >>= 1) s += __shfl_down_sync(0xffffffffu, s, off);
        if (t == 0) out[g] = s + fc2b[0];
    }
}

// ---------------------------------------------------------------- launch
extern "C" void kernel_launch(void* const* d_in, const int* in_sizes, int n_in,
                              void* d_out, int out_size) {
    const float* x     = (const float*)d_in[0];
    const int*   ei    = (const int*)d_in[1];
    const int*   batch = (const int*)d_in[2];
    const float* W0    = (const float*)d_in[3];
    const float* b0    = (const float*)d_in[4];
    const float* W1    = (const float*)d_in[5];
    const float* b1    = (const float*)d_in[6];
    const float* W2    = (const float*)d_in[7];
    const float* b2    = (const float*)d_in[8];
    const float* fc1w  = (const float*)d_in[9];
    const float* fc1b  = (const float*)d_in[10];
    const float* fc2w  = (const float*)d_in[11];
    const float* fc2b  = (const float*)d_in[12];
    float* out = (float*)d_out;

    // CSR build (g_cnt enters zeroed: zero-init at load, re-zeroed by fill_k)
    hist_k<<<(N_EDGES / 8 + 255) / 256, 256>>>(ei);
    scan1_k<<<NB, 1024>>>(x);
    scan3_k<<<(N_NODES + 255) / 256, 256>>>();
    fill_k<<<(N_EDGES / 8 + 255) / 256, 256>>>(ei);

    const int AGG_BLOCKS  = (N_NODES * 32 + 255) / 256;
    const int GEMM_BLOCKS = (N_NODES + 127) / 128;

    // Layer 0 (fused 3-ch aggregate + dense, bf16 out)
    agg_x_gemm0_k<<<(N_NODES * 8 + 255) / 256, 256>>>(W0, b0);
    // Layer 1
    gemm64_k<<<GEMM_BLOCKS, 256>>>(W1);
    agg_k<true><<<AGG_BLOCKS, 256>>>(b1);
    // Layer 2
    gemm64_k<<<GEMM_BLOCKS, 256>>>(W2);
    agg_k<false><<<AGG_BLOCKS, 256>>>(b2);

    // Pool + head
    poolfc_k<<<NGRAPH, 256>>>(batch, fc1w, fc1b, fc2w, fc2b, out);
}

// round 10
// speedup vs baseline: 1.1659x; 1.0119x over previous
#include <cuda_runtime.h>
#include <cuda_bf16.h>
#include <cstdint>

#define N_NODES 100000
#define N_EDGES 1600000
#define HID 64
#define NGRAPH 128
#define DENSE 128
#define SCAN_BLK 4096
#define NB ((N_NODES + SCAN_BLK - 1) / SCAN_BLK)   // 25 blocks (all co-resident)

// Scratch
__device__ float           g_buf0[N_NODES * HID];  // fp32 h (layer-2 agg out, pool input)
__device__ __nv_bfloat16   g_hb[N_NODES * HID];    // bf16 h (gemm input)
__device__ __nv_bfloat16   g_gath[N_NODES * HID];  // (h@W)*dinv, bf16 gather buffer
__device__ int    g_cnt[N_NODES];                  // zeroed at end of fill_k each call
__device__ int    g_rowptr[N_NODES + 1];
__device__ int    g_cursor[N_NODES];
__device__ int    g_col[N_EDGES];
__device__ float  g_dinv[N_NODES];
__device__ float4 g_xd[N_NODES];                   // x * dinv[src], padded
__device__ unsigned long long g_aggflag[NB];       // (1<<40)|aggregate; zeroed in fill_k

#define AGG_FLAG (1ull << 40)

// ---------------------------------------------------------------- CSR build
// Fire-and-forget histogram (REDG). 4 edges per thread.
__global__ void hist_k(const int* __restrict__ ei) {
    int i = blockIdx.x * blockDim.x + threadIdx.x;
    if (i < N_EDGES / 4) {
        int4 d = ((const int4*)(ei + N_EDGES))[i];
        atomicAdd(&g_cnt[d.x], 1);
        atomicAdd(&g_cnt[d.y], 1);
        atomicAdd(&g_cnt[d.z], 1);
        atomicAdd(&g_cnt[d.w], 1);
    }
}

// Single-pass scan: local exclusive scan + cross-block offset via flagged
// aggregates (all NB=25 blocks co-resident on 148 SMs -> no deadlock).
// Writes rowptr, cursor, dinv, xd in one pass.
__global__ void scan_k(const float* __restrict__ x) {
    __shared__ int sh[1024];
    __shared__ int off_s;
    int tid = threadIdx.x;
    int bid = blockIdx.x;
    int base = bid * SCAN_BLK;
    int v[4];
    int local = 0;
#pragma unroll
    for (int q = 0; q < 4; q++) {
        int i = base + tid * 4 + q;
        v[q] = (i < N_NODES) ? g_cnt[i] : 0;
        local += v[q];
    }
    sh[tid] = local;
    for (int off = 1; off < 1024; off <<= 1) {
        __syncthreads();
        int t = (tid >= off) ? sh[tid - off] : 0;
        __syncthreads();
        sh[tid] += t;
    }
    __syncthreads();
    int total = sh[1023];

    // Publish this block's aggregate, then sum predecessors' aggregates.
    if (tid < 32) {
        if (tid == 0) {
            __threadfence();
            g_aggflag[bid] = AGG_FLAG | (unsigned long long)total;
        }
        unsigned long long av = 0;
        if (tid < bid) {
            volatile unsigned long long* p = &g_aggflag[tid];
            do { av = *p; } while (!(av & AGG_FLAG));
        }
        int pre = (int)(av & 0xFFFFFFFFull);
#pragma unroll
        for (int o = 16; o; o >>= 1) pre += __shfl_xor_sync(0xffffffffu, pre, o);
        if (tid == 0) off_s = pre;
    }
    __syncthreads();
    int run = off_s + sh[tid] - local;
#pragma unroll
    for (int q = 0; q < 4; q++) {
        int i = base + tid * 4 + q;
        if (i < N_NODES) {
            g_rowptr[i] = run;
            g_cursor[i] = run;
            run += v[q];
            float di = rsqrtf((float)(v[q] + 1));   // +1 self loop
            g_dinv[i] = di;
            float x0 = x[i * 3 + 0], x1 = x[i * 3 + 1], x2 = x[i * 3 + 2];
            g_xd[i] = make_float4(x0 * di, x1 * di, x2 * di, 0.f);
        }
    }
    if (bid == NB - 1 && tid == 1023) g_rowptr[N_NODES] = run;
}

// Cursor-based fill, 4 edges per thread; re-zeroes g_cnt + aggflags at tail.
__global__ void fill_k(const int* __restrict__ ei) {
    int i = blockIdx.x * blockDim.x + threadIdx.x;
    if (i < N_EDGES / 4) {
        int4 s = ((const int4*)ei)[i];
        int4 d = ((const int4*)(ei + N_EDGES))[i];
        g_col[atomicAdd(&g_cursor[d.x], 1)] = s.x;
        g_col[atomicAdd(&g_cursor[d.y], 1)] = s.y;
        g_col[atomicAdd(&g_cursor[d.z], 1)] = s.z;
        g_col[atomicAdd(&g_cursor[d.w], 1)] = s.w;
    }
    if (i < N_NODES / 4) ((int4*)g_cnt)[i] = make_int4(0, 0, 0, 0);
    if (i < NB) g_aggflag[i] = 0ull;
}

// ---------------------------------------------------------------- Layer 0 (fused)
// 8 lanes per node: gather-reduce xd (3ch), then emit bf16 relu(aggx@W0+b0).
__global__ void agg_x_gemm0_k(const float* __restrict__ W0, const float* __restrict__ b0) {
    __shared__ float Ws[3 * HID];
    __shared__ float Bs[HID];
    int t = threadIdx.x;
    if (t < 3 * HID) Ws[t] = W0[t];
    if (t < HID) Bs[t] = b0[t];
    __syncthreads();
    int node = (blockIdx.x * blockDim.x + t) >> 3;
    int l8   = t & 7;
    if (node >= N_NODES) return;
    int s = g_rowptr[node];
    int e = g_rowptr[node + 1];
    float ax = 0.f, ay = 0.f, az = 0.f;
    if (l8 == 0) { float4 v = g_xd[node]; ax = v.x; ay = v.y; az = v.z; }
    for (int idx = s + l8; idx < e; idx += 8) {
        float4 v = g_xd[g_col[idx]];
        ax += v.x; ay += v.y; az += v.z;
    }
#pragma unroll
    for (int off = 1; off < 8; off <<= 1) {
        ax += __shfl_xor_sync(0xffffffffu, ax, off);
        ay += __shfl_xor_sync(0xffffffffu, ay, off);
        az += __shfl_xor_sync(0xffffffffu, az, off);
    }
    float di = g_dinv[node];
    ax *= di; ay *= di; az *= di;
    int c0 = l8 * 8;
    float o[8];
#pragma unroll
    for (int q = 0; q < 8; q++) {
        int c = c0 + q;
        o[q] = fmaxf(fmaf(ax, Ws[c], fmaf(ay, Ws[HID + c], fmaf(az, Ws[2 * HID + c], Bs[c]))), 0.f);
    }
    __nv_bfloat162 p0 = __floats2bfloat162_rn(o[0], o[1]);
    __nv_bfloat162 p1 = __floats2bfloat162_rn(o[2], o[3]);
    __nv_bfloat162 p2 = __floats2bfloat162_rn(o[4], o[5]);
    __nv_bfloat162 p3 = __floats2bfloat162_rn(o[6], o[7]);
    uint4 pk;
    pk.x = *(uint32_t*)&p0; pk.y = *(uint32_t*)&p1;
    pk.z = *(uint32_t*)&p2; pk.w = *(uint32_t*)&p3;
    *(uint4*)&g_hb[node * HID + c0] = pk;
}

// ---------------------------------------------------------------- GEMM (tensor core)
// g_gath[r] = bf16( (hb @ W)[r] * dinv[r] ), hb bf16, W fp32->bf16, fp32 accum.
#define AS_LD 72   // bf16 stride (64 + 8 pad)
__global__ void gemm64_k(const float* __restrict__ W) {
    __shared__ __nv_bfloat16 As[128 * AS_LD];
    __shared__ __nv_bfloat16 Wsm[64 * AS_LD];
    int t = threadIdx.x;
    int warp = t >> 5, lane = t & 31;
    int rb = blockIdx.x * 128;

#pragma unroll
    for (int q = 0; q < 16; q++) {
        int i = t + q * 256;
        int r = i >> 6, c = i & 63;
        Wsm[r * AS_LD + c] = __float2bfloat16(W[i]);
    }
#pragma unroll
    for (int q = 0; q < 4; q++) {
        int i = t + q * 256;
        int r = i >> 3, seg = i & 7;
        uint4 v = make_uint4(0, 0, 0, 0);
        if (rb + r < N_NODES) v = ((const uint4*)&g_hb[(rb + r) * HID])[seg];
        *(uint4*)&As[r * AS_LD + seg * 8] = v;
    }
    __syncthreads();

    int wrow = warp * 16;
    float acc[8][4];
#pragma unroll
    for (int nb = 0; nb < 8; nb++)
#pragma unroll
        for (int q = 0; q < 4; q++) acc[nb][q] = 0.f;

#pragma unroll
    for (int ks = 0; ks < 4; ks++) {
        uint32_t a0, a1, a2, a3;
        {
            const __nv_bfloat16* ap = &As[(wrow + (lane & 15)) * AS_LD + ks * 16 + (lane >> 4) * 8];
            uint32_t addr = (uint32_t)__cvta_generic_to_shared(ap);
            asm volatile("ldmatrix.sync.aligned.m8n8.x4.shared.b16 {%0,%1,%2,%3}, [%4];"
                         : "=r"(a0), "=r"(a1), "=r"(a2), "=r"(a3) : "r"(addr));
        }
#pragma unroll
        for (int nb = 0; nb < 8; nb++) {
            uint32_t b0, b1;
            const __nv_bfloat16* bp = &Wsm[(ks * 16 + (lane & 15)) * AS_LD + nb * 8];
            uint32_t baddr = (uint32_t)__cvta_generic_to_shared(bp);
            asm volatile("ldmatrix.sync.aligned.m8n8.x2.trans.shared.b16 {%0,%1}, [%2];"
                         : "=r"(b0), "=r"(b1) : "r"(baddr));
            asm volatile(
                "mma.sync.aligned.m16n8k16.row.col.f32.bf16.bf16.f32 "
                "{%0,%1,%2,%3},{%4,%5,%6,%7},{%8,%9},{%0,%1,%2,%3};"
                : "+f"(acc[nb][0]), "+f"(acc[nb][1]), "+f"(acc[nb][2]), "+f"(acc[nb][3])
                : "r"(a0), "r"(a1), "r"(a2), "r"(a3), "r"(b0), "r"(b1));
        }
    }

    int r0 = rb + wrow + (lane >> 2);
    int r1 = r0 + 8;
    float di0 = (r0 < N_NODES) ? g_dinv[r0] : 0.f;
    float di1 = (r1 < N_NODES) ? g_dinv[r1] : 0.f;
    int cb = (lane & 3) * 2;
#pragma unroll
    for (int nb = 0; nb < 8; nb++) {
        int c = nb * 8 + cb;
        if (r0 < N_NODES) {
            __nv_bfloat162 p = __floats2bfloat162_rn(acc[nb][0] * di0, acc[nb][1] * di0);
            *(uint32_t*)&g_gath[r0 * HID + c] = *(uint32_t*)&p;
        }
        if (r1 < N_NODES) {
            __nv_bfloat162 p = __floats2bfloat162_rn(acc[nb][2] * di1, acc[nb][3] * di1);
            *(uint32_t*)&g_gath[r1 * HID + c] = *(uint32_t*)&p;
        }
    }
}

// ---------------------------------------------------------------- Aggregation
// One warp per dst node; 4 groups x 8 lanes, direct g_col loads, bf16 rows,
// fp32 accumulate.
template <bool OUT_BF16>
__global__ void agg_k(const float* __restrict__ bias) {
    int w    = (blockIdx.x * blockDim.x + threadIdx.x) >> 5;
    int lane = threadIdx.x & 31;
    if (w >= N_NODES) return;
    int grp = lane >> 3;
    int l8  = lane & 7;
    int ch0 = l8 * 8;
    int s = g_rowptr[w];
    int e = g_rowptr[w + 1];

    float2 a0 = make_float2(0.f, 0.f), a1 = a0, a2 = a0, a3 = a0;

#define ACC_ROW(SRC)                                                          \
    {                                                                         \
        uint4 pk = *(const uint4*)&g_gath[(SRC) * HID + ch0];                 \
        float2 f0 = __bfloat1622float2(*(__nv_bfloat162*)&pk.x);              \
        float2 f1 = __bfloat1622float2(*(__nv_bfloat162*)&pk.y);              \
        float2 f2 = __bfloat1622float2(*(__nv_bfloat162*)&pk.z);              \
        float2 f3 = __bfloat1622float2(*(__nv_bfloat162*)&pk.w);              \
        a0.x += f0.x; a0.y += f0.y; a1.x += f1.x; a1.y += f1.y;               \
        a2.x += f2.x; a2.y += f2.y; a3.x += f3.x; a3.y += f3.y;               \
    }

    int idx = s + grp;
    for (; idx + 12 < e; idx += 16) {      // 4 edges per group in flight
        int s0 = g_col[idx];
        int s1 = g_col[idx + 4];
        int s2 = g_col[idx + 8];
        int s3 = g_col[idx + 12];
        ACC_ROW(s0); ACC_ROW(s1); ACC_ROW(s2); ACC_ROW(s3);
    }
    for (; idx < e; idx += 4) {
        int s0 = g_col[idx];
        ACC_ROW(s0);
    }
#undef ACC_ROW

#pragma unroll
    for (int off = 8; off <= 16; off <<= 1) {
        a0.x += __shfl_xor_sync(0xffffffffu, a0.x, off);
        a0.y += __shfl_xor_sync(0xffffffffu, a0.y, off);
        a1.x += __shfl_xor_sync(0xffffffffu, a1.x, off);
        a1.y += __shfl_xor_sync(0xffffffffu, a1.y, off);
        a2.x += __shfl_xor_sync(0xffffffffu, a2.x, off);
        a2.y += __shfl_xor_sync(0xffffffffu, a2.y, off);
        a3.x += __shfl_xor_sync(0xffffffffu, a3.x, off);
        a3.y += __shfl_xor_sync(0xffffffffu, a3.y, off);
    }

    if (grp == 0) {
        uint4 pk = *(const uint4*)&g_gath[w * HID + ch0];   // self loop
        float2 f0 = __bfloat1622float2(*(__nv_bfloat162*)&pk.x);
        float2 f1 = __bfloat1622float2(*(__nv_bfloat162*)&pk.y);
        float2 f2 = __bfloat1622float2(*(__nv_bfloat162*)&pk.z);
        float2 f3 = __bfloat1622float2(*(__nv_bfloat162*)&pk.w);
        a0.x += f0.x; a0.y += f0.y; a1.x += f1.x; a1.y += f1.y;
        a2.x += f2.x; a2.y += f2.y; a3.x += f3.x; a3.y += f3.y;

        float di = g_dinv[w];
        float4 bA = *(const float4*)&bias[ch0];
        float4 bB = *(const float4*)&bias[ch0 + 4];
        float o0 = fmaxf(fmaf(a0.x, di, bA.x), 0.f);
        float o1 = fmaxf(fmaf(a0.y, di, bA.y), 0.f);
        float o2 = fmaxf(fmaf(a1.x, di, bA.z), 0.f);
        float o3 = fmaxf(fmaf(a1.y, di, bA.w), 0.f);
        float o4 = fmaxf(fmaf(a2.x, di, bB.x), 0.f);
        float o5 = fmaxf(fmaf(a2.y, di, bB.y), 0.f);
        float o6 = fmaxf(fmaf(a3.x, di, bB.z), 0.f);
        float o7 = fmaxf(fmaf(a3.y, di, bB.w), 0.f);
        if (OUT_BF16) {
            __nv_bfloat162 p0 = __floats2bfloat162_rn(o0, o1);
            __nv_bfloat162 p1 = __floats2bfloat162_rn(o2, o3);
            __nv_bfloat162 p2 = __floats2bfloat162_rn(o4, o5);
            __nv_bfloat162 p3 = __floats2bfloat162_rn(o6, o7);
            uint4 pko;
            pko.x = *(uint32_t*)&p0; pko.y = *(uint32_t*)&p1;
            pko.z = *(uint32_t*)&p2; pko.w = *(uint32_t*)&p3;
            *(uint4*)&g_hb[w * HID + ch0] = pko;
        } else {
            *(float4*)&g_buf0[w * HID + ch0]     = make_float4(o0, o1, o2, o3);
            *(float4*)&g_buf0[w * HID + ch0 + 4] = make_float4(o4, o5, o6, o7);
        }
    }
}

// ---------------------------------------------------------------- Pool + head (fused)
__global__ void poolfc_k(const int* __restrict__ batch,
                         const float* __restrict__ fc1w, const float* __restrict__ fc1b,
                         const float* __restrict__ fc2w, const float* __restrict__ fc2b,
                         float* __restrict__ out) {
    int g = blockIdx.x, t = threadIdx.x;   // 128 blocks x 256 thr
    __shared__ int lo_s, hi_s;
    if (t == 0) {
        int lo = 0, hi = N_NODES;
        while (lo < hi) { int m = (lo + hi) >> 1; if (batch[m] < g) lo = m + 1; else hi = m; }
        lo_s = lo;
        int lo2 = lo, hi2 = N_NODES;
        while (lo2 < hi2) { int m = (lo2 + hi2) >> 1; if (batch[m] < g + 1) lo2 = m + 1; else hi2 = m; }
        hi_s = lo2;
    }
    __syncthreads();
    int lo = lo_s, hi = hi_s;
    int c = t & 63, rg = t >> 6;
    float acc = 0.f;
    for (int r = lo + rg; r < hi; r += 4) acc += g_buf0[r * HID + c];
    __shared__ float sh[256];
    __shared__ float p[64];
    sh[t] = acc;
    __syncthreads();
    if (t < 64) {
        float s = sh[t] + sh[t + 64] + sh[t + 128] + sh[t + 192];
        float cntf = (float)(hi - lo);
        if (cntf < 1.f) cntf = 1.f;
        p[t] = s / cntf;
    }
    __syncthreads();
    float v = 0.f;
    if (t < DENSE) {
        float a = fc1b[t];
#pragma unroll
        for (int k = 0; k < 64; k++) a = fmaf(p[k], fc1w[k * DENSE + t], a);
        v = fmaxf(a, 0.f) * fc2w[t];
    }
    __syncthreads();
    sh[t] = v;
    __syncthreads();
    if (t < 64) sh[t] += sh[t + 64];
    __syncthreads();
    if (t < 32) {
        float s = sh[t] + sh[t + 32];
#pragma unroll
        for (int off = 16; off; off >>= 1) s += __shfl_down_sync(0xffffffffu, s, off);
        if (t == 0) out[g] = s + fc2b[0];
    }
}

// ---------------------------------------------------------------- launch
extern "C" void kernel_launch(void* const* d_in, const int* in_sizes, int n_in,
                              void* d_out, int out_size) {
    const float* x     = (const float*)d_in[0];
    const int*   ei    = (const int*)d_in[1];
    const int*   batch = (const int*)d_in[2];
    const float* W0    = (const float*)d_in[3];
    const float* b0    = (const float*)d_in[4];
    const float* W1    = (const float*)d_in[5];
    const float* b1    = (const float*)d_in[6];
    const float* W2    = (const float*)d_in[7];
    const float* b2    = (const float*)d_in[8];
    const float* fc1w  = (const float*)d_in[9];
    const float* fc1b  = (const float*)d_in[10];
    const float* fc2w  = (const float*)d_in[11];
    const float* fc2b  = (const float*)d_in[12];
    float* out = (float*)d_out;

    // CSR build (g_cnt and g_aggflag enter zeroed: zero-init at load,
    // re-zeroed by fill_k each call)
    hist_k<<<(N_EDGES / 4 + 255) / 256, 256>>>(ei);
    scan_k<<<NB, 1024>>>(x);
    fill_k<<<(N_EDGES / 4 + 255) / 256, 256>>>(ei);

    const int AGG_BLOCKS  = (N_NODES * 32 + 255) / 256;
    const int GEMM_BLOCKS = (N_NODES + 127) / 128;

    // Layer 0 (fused 3-ch aggregate + dense, bf16 out)
    agg_x_gemm0_k<<<(N_NODES * 8 + 255) / 256, 256>>>(W0, b0);
    // Layer 1
    gemm64_k<<<GEMM_BLOCKS, 256>>>(W1);
    agg_k<true><<<AGG_BLOCKS, 256>>>(b1);
    // Layer 2
    gemm64_k<<<GEMM_BLOCKS, 256>>>(W2);
    agg_k<false><<<AGG_BLOCKS, 256>>>(b2);

    // Pool + head
    poolfc_k<<<NGRAPH, 256>>>(batch, fc1w, fc1b, fc2w, fc2b, out);
}